// round 1
// baseline (speedup 1.0000x reference)
#include <cuda_runtime.h>

// TransConv via parity decomposition -> 4 implicit GEMMs.
//   out[n, co, 2i+ph, 2j+pw] = b[co]
//     + sum_{dh,dw in {0,1}, ci} x[n, ci, i+ph-1+dh, j+pw-1+dw] * W[ph+2dh, pw+2dw, ci, co]
// Shapes: x[32,128,64,64], W[4,4,128,128] (HWIO), b[128], out[32,128,128,128].
//
// Per block: one parity class, one batch n, spatial tile 8(i) x 16(j) = 128 "M" rows,
// all 128 co ("N"), K = 4 taps x 128 ci done as 32 chunks of BK=16.
// 256 threads, 8x8 fp32 micro-tile per thread.
// Thread map: mt = tid&15 -> j lane (store coalescing), nt = tid>>4 -> co group.
//   a-frag: m = r*16 + mt  (i=r, j=mt)  -> LDS.32 x8, broadcast across nt
//   b-frag: co = nt*4 + [0,4) and 64 + nt*4 + [0,4) -> 2x LDS.128
// Grid: blockIdx = tile*4 + (ph*2+pw): sibling-parity blocks run adjacently so
// their stride-2 stores merge into full 128B lines in L2 before DRAM writeback.

#define CIN 128
#define COUT 128
#define INH 64
#define INW 64
#define OUTH 128
#define OUTW 128

__global__ __launch_bounds__(256, 2)
void tconv_fp32_kernel(const float* __restrict__ x,
                       const float* __restrict__ Wt,
                       const float* __restrict__ bias,
                       float* __restrict__ out)
{
    __shared__ float As[16][128];   // [kk][m]   m = i*16 + j
    __shared__ float Bs[16][128];   // [kk][co]

    const int tid = threadIdx.x;
    const int mt  = tid & 15;       // j lane
    const int nt  = tid >> 4;       // co group

    const int blk  = blockIdx.x;
    const int par  = blk & 3;
    const int pw   = par & 1;
    const int ph   = par >> 1;
    const int tile = blk >> 2;
    const int n    = tile >> 5;            // 32 tiles per batch
    const int rem  = tile & 31;
    const int i0   = (rem >> 2) * 8;       // 8 i-tiles of height 8
    const int j0   = (rem & 3) * 16;       // 4 j-tiles of width 16

    float acc[8][8];
#pragma unroll
    for (int r = 0; r < 8; ++r)
#pragma unroll
        for (int c = 0; c < 8; ++c) acc[r][c] = 0.f;

    const float* xn = x + (size_t)n * CIN * INH * INW;

    for (int t = 0; t < 4; ++t) {
        const int dh = t >> 1, dw = t & 1;
        const int kh = ph + 2 * dh;
        const int kw = pw + 2 * dw;
        const int ih_base = i0 + ph - 1 + dh;
        const int iw_base = j0 + pw - 1 + dw;
        const float* Wb = Wt + (size_t)(kh * 4 + kw) * CIN * COUT;

        for (int ci0 = 0; ci0 < CIN; ci0 += 16) {
            __syncthreads();
            // Cooperative load: 2048 elems each of As and Bs, 8 per thread.
#pragma unroll
            for (int e = 0; e < 8; ++e) {
                const int flat = e * 256 + tid;
                const int kk = flat >> 7;      // [0,16)
                const int m  = flat & 127;     // [0,128)
                const int ii = m >> 4;
                const int jj = m & 15;
                const int ihx = ih_base + ii;
                const int iwx = iw_base + jj;
                float v = 0.f;
                if ((unsigned)ihx < (unsigned)INH && (unsigned)iwx < (unsigned)INW)
                    v = __ldg(&xn[((ci0 + kk) * INH + ihx) * INW + iwx]);
                As[kk][m] = v;
                Bs[kk][m] = __ldg(&Wb[(ci0 + kk) * COUT + m]);
            }
            __syncthreads();

#pragma unroll
            for (int kk = 0; kk < 16; ++kk) {
                float a[8], bb[8];
#pragma unroll
                for (int r = 0; r < 8; ++r) a[r] = As[kk][r * 16 + mt];
                const float4 b0 = *(const float4*)&Bs[kk][nt * 4];
                const float4 b1 = *(const float4*)&Bs[kk][nt * 4 + 64];
                bb[0] = b0.x; bb[1] = b0.y; bb[2] = b0.z; bb[3] = b0.w;
                bb[4] = b1.x; bb[5] = b1.y; bb[6] = b1.z; bb[7] = b1.w;
#pragma unroll
                for (int r = 0; r < 8; ++r)
#pragma unroll
                    for (int c = 0; c < 8; ++c)
                        acc[r][c] = fmaf(a[r], bb[c], acc[r][c]);
            }
        }
    }

    // Epilogue: direct stores. Lanes vary mt -> consecutive j -> ow stride 2.
    float bfrag[8];
#pragma unroll
    for (int c = 0; c < 8; ++c) {
        const int co = (c < 4) ? (nt * 4 + c) : (64 + nt * 4 + (c - 4));
        bfrag[c] = __ldg(&bias[co]);
    }

    const int ow = 2 * (j0 + mt) + pw;
#pragma unroll
    for (int r = 0; r < 8; ++r) {
        const int oh = 2 * (i0 + r) + ph;
#pragma unroll
        for (int c = 0; c < 8; ++c) {
            const int co = (c < 4) ? (nt * 4 + c) : (64 + nt * 4 + (c - 4));
            out[(((size_t)n * COUT + co) * OUTH + oh) * OUTW + ow] = acc[r][c] + bfrag[c];
        }
    }
}

extern "C" void kernel_launch(void* const* d_in, const int* in_sizes, int n_in,
                              void* d_out, int out_size)
{
    const float* x  = (const float*)d_in[0];
    const float* Wt = (const float*)d_in[1];
    const float* b  = (const float*)d_in[2];
    float* out = (float*)d_out;

    // 32 n * 32 tiles * 4 parities = 4096 blocks
    tconv_fp32_kernel<<<4096, 256>>>(x, Wt, b, out);
}

// round 4
// speedup vs baseline: 2.6455x; 2.6455x over previous
#include <cuda_runtime.h>
#include <cuda_bf16.h>
#include <cstdint>

#define NB    32
#define CIN   128
#define COUT  128
#define INH   64
#define INW   64
#define OUTHW 16384   // 128*128

// ---------------- scratch (device globals: allocation-free) ----------------
__device__ __nv_bfloat16 g_xhi[(size_t)NB * INH * INW * CIN];   // NHWC
__device__ __nv_bfloat16 g_xlo[(size_t)NB * INH * INW * CIN];   // NHWC
__device__ __nv_bfloat16 g_bext[(size_t)4 * COUT * 1536];       // [par][co][k]

// ---------------- helpers ----------------
__device__ __forceinline__ uint32_t smem_u32(const void* p) {
    uint32_t a;
    asm("{ .reg .u64 t; cvta.to.shared.u64 t, %1; cvt.u32.u64 %0, t; }" : "=r"(a) : "l"(p));
    return a;
}
__device__ __forceinline__ void cp_async16(uint32_t dst, const void* src, uint32_t sz) {
    asm volatile("cp.async.cg.shared.global [%0], [%1], 16, %2;"
                 :: "r"(dst), "l"(src), "r"(sz) : "memory");
}
#define CP_COMMIT() asm volatile("cp.async.commit_group;" ::: "memory")
#define CP_WAIT(n)  asm volatile("cp.async.wait_group %0;" :: "n"(n) : "memory")

__device__ __forceinline__ void ldsm_x4(uint32_t* r, uint32_t addr) {
    asm volatile("ldmatrix.sync.aligned.m8n8.x4.shared.b16 {%0,%1,%2,%3}, [%4];"
                 : "=r"(r[0]), "=r"(r[1]), "=r"(r[2]), "=r"(r[3]) : "r"(addr));
}
__device__ __forceinline__ void mma_bf16(float* c, const uint32_t* a, const uint32_t* b) {
    asm volatile(
        "mma.sync.aligned.m16n8k16.row.col.f32.bf16.bf16.f32 "
        "{%0,%1,%2,%3}, {%4,%5,%6,%7}, {%8,%9}, {%0,%1,%2,%3};"
        : "+f"(c[0]), "+f"(c[1]), "+f"(c[2]), "+f"(c[3])
        : "r"(a[0]), "r"(a[1]), "r"(a[2]), "r"(a[3]), "r"(b[0]), "r"(b[1]));
}

// =================== kernel 1: x fp32 NCHW -> bf16 hi/lo NHWC ===================
__global__ __launch_bounds__(256) void convert_x_kernel(const float* __restrict__ x) {
    __shared__ float tile[128][65];
    const int bid = blockIdx.x;
    const int n = bid >> 6, ihh = bid & 63;
    const int tid = threadIdx.x;

#pragma unroll 4
    for (int e = 0; e < 32; ++e) {
        int flat = e * 256 + tid;
        int ci = flat >> 6, iw = flat & 63;
        tile[ci][iw] = x[(((size_t)n * CIN + ci) * INH + ihh) * INW + iw];
    }
    __syncthreads();
    const size_t ob = (((size_t)n * INH + ihh) * INW) * CIN;
#pragma unroll 4
    for (int e = 0; e < 32; ++e) {
        int flat = e * 256 + tid;
        int iw = flat >> 7, ci = flat & 127;
        float v = tile[ci][iw];
        __nv_bfloat16 hv = __float2bfloat16(v);
        __nv_bfloat16 lv = __float2bfloat16(v - __bfloat162float(hv));
        g_xhi[ob + (size_t)iw * CIN + ci] = hv;
        g_xlo[ob + (size_t)iw * CIN + ci] = lv;
    }
}

// =================== kernel 2: B_ext [par][co][k=1536] ===================
// k = s*512 + t*128 + ci ; s0 -> W_hi (pairs x_hi), s1 -> W_lo (x_hi), s2 -> W_hi (x_lo)
__global__ __launch_bounds__(256) void build_bext_kernel(const float* __restrict__ W) {
    const int idx = blockIdx.x * 256 + threadIdx.x;   // < 786432
    const int k = idx % 1536;
    const int rco = idx / 1536;
    const int co = rco & 127, par = rco >> 7;
    const int s = k / 512, k5 = k % 512, t = k5 >> 7, ci = k5 & 127;
    const int dh = t >> 1, dw = t & 1, ph = par >> 1, pw = par & 1;
    const int kh = ph + 2 * dh, kw = pw + 2 * dw;
    const float w = W[(((size_t)(kh * 4 + kw)) * CIN + ci) * COUT + co];
    const __nv_bfloat16 hv = __float2bfloat16(w);
    g_bext[idx] = (s == 1) ? __float2bfloat16(w - __bfloat162float(hv)) : hv;
}

// =================== kernel 3: mma.sync GEMM ===================
// Block = (parity, n, itile). M=128 (2 i-rows x 64 j), N=128 co, K'=1536, 24 chunks of 64.
// 8 warps: warp_m = wid>>2 (2), warp_n = wid&3 (4). Warp tile 64x32 = 4x4 m16n8k16.
__global__ __launch_bounds__(256, 2) void tconv_gemm(const float* __restrict__ bias,
                                                     float* __restrict__ out) {
    extern __shared__ char dynsmem[];
    const uint32_t tiles = (smem_u32(dynsmem) + 1023u) & ~1023u;  // 64KB, 2 stages

    const int tid = threadIdx.x, wid = tid >> 5, lane = tid & 31;
    const int blk = blockIdx.x;
    const int par = blk & 3, rest = blk >> 2;
    const int itile = rest & 31, n = rest >> 5;
    const int ph = par >> 1, pw = par & 1;
    const int warp_m = wid >> 2, warp_n = wid & 3;

    float acc[4][4][4];
#pragma unroll
    for (int mt = 0; mt < 4; ++mt)
#pragma unroll
        for (int nt = 0; nt < 4; ++nt)
#pragma unroll
            for (int q = 0; q < 4; ++q) acc[mt][nt][q] = 0.f;

    // ---- cp.async tile issue for chunk c into stage c&1 ----
    auto issue = [&](int c) {
        const int s = c >> 3, t = (c >> 1) & 3, h = c & 1;
        const int dh = t >> 1, dw = t & 1;
        const uint32_t abase = tiles + (uint32_t)(c & 1) * 32768u;
        const uint32_t bbase = abase + 16384u;
        const __nv_bfloat16* xs = (s < 2) ? g_xhi : g_xlo;
        const int ih_off = itile * 2 + ph - 1 + dh;
        const int iw_off = pw - 1 + dw;
        const int kb = s * 512 + t * 128 + h * 64;
#pragma unroll
        for (int e = 0; e < 8; ++e) {
            const int idx = e * 256 + tid;
            const int row = (idx >> 3) & 127, s16 = idx & 7;
            uint32_t so = (uint32_t)(row * 128 + s16 * 16);
            so ^= (so >> 3) & 0x70;                       // SW128 swizzle
            if (idx < 1024) {                             // A: 128 m-rows x 64 k
                const int i_loc = row >> 6, j = row & 63;
                const int ihx = ih_off + i_loc, iwx = iw_off + j;
                const bool ok = ((unsigned)ihx < 64u) & ((unsigned)iwx < 64u);
                const __nv_bfloat16* src = ok
                    ? xs + (((size_t)n * INH + ihx) * INW + iwx) * CIN + h * 64 + s16 * 8
                    : xs;                                 // valid dummy, sz=0 zero-fills
                cp_async16(abase + so, src, ok ? 16u : 0u);
            } else {                                      // B: 128 co-rows x 64 k
                const __nv_bfloat16* src =
                    g_bext + ((size_t)(par * COUT + row)) * 1536 + kb + s16 * 8;
                cp_async16(bbase + so, src, 16u);
            }
        }
        CP_COMMIT();
    };

    // ---- compute chunk c from stage c&1 ----
    auto compute = [&](int c) {
        const uint32_t abase = tiles + (uint32_t)(c & 1) * 32768u;
        const uint32_t bbase = abase + 16384u;
        const int arow = warp_m * 64 + (lane & 15);       // + mt*16
        const int acp0 = lane >> 4;                       // + 2*s
        const int bmtx = lane >> 3, brlo = lane & 7;
        const int brow0 = warp_n * 32 + ((bmtx >> 1) << 3) + brlo;   // + p*16
        const int bcp0 = bmtx & 1;                        // + 2*s
#pragma unroll
        for (int s = 0; s < 4; ++s) {
            uint32_t a[4][4];
#pragma unroll
            for (int mt = 0; mt < 4; ++mt) {
                const int r = arow + mt * 16;
                const uint32_t chunk = (uint32_t)((acp0 + 2 * s) ^ (r & 7));
                ldsm_x4(a[mt], abase + (uint32_t)r * 128u + chunk * 16u);
            }
            uint32_t b[2][4];                             // p -> {b0n0,b1n0,b0n1,b1n1}
#pragma unroll
            for (int p = 0; p < 2; ++p) {
                const int r = brow0 + p * 16;
                const uint32_t chunk = (uint32_t)((bcp0 + 2 * s) ^ (r & 7));
                ldsm_x4(b[p], bbase + (uint32_t)r * 128u + chunk * 16u);
            }
#pragma unroll
            for (int mt = 0; mt < 4; ++mt)
#pragma unroll
                for (int nt = 0; nt < 4; ++nt)
                    mma_bf16(acc[mt][nt], a[mt], &b[nt >> 1][(nt & 1) * 2]);
        }
    };

    issue(0);
    issue(1);
#pragma unroll 1
    for (int c = 0; c < 24; ++c) {
        if (c < 23) { CP_WAIT(1); } else { CP_WAIT(0); }
        __syncthreads();
        compute(c);
        __syncthreads();
        if (c + 2 < 24) issue(c + 2);
    }

    // ---- epilogue: registers -> gmem ----
    // acc reg q: q0:(g, 2t) q1:(g, 2t+1) q2:(g+8, 2t) q3:(g+8, 2t+1)
    const int g = lane >> 2, tg = lane & 3;
    const int oh0 = 2 * (itile * 2 + warp_m) + ph;        // i_loc == warp_m for all rows
    float* const ob = out + (size_t)n * COUT * OUTHW + (size_t)oh0 * 128 + pw;
#pragma unroll
    for (int nt = 0; nt < 4; ++nt) {
        const int co = warp_n * 32 + nt * 8 + 2 * tg;
        const float b0 = __ldg(&bias[co]), b1 = __ldg(&bias[co + 1]);
        float* const oc0 = ob + (size_t)co * OUTHW;
        float* const oc1 = oc0 + OUTHW;
#pragma unroll
        for (int mt = 0; mt < 4; ++mt) {
            const int j0 = mt * 16 + g;                   // j of rows (g) ; j0+8 for g+8
            oc0[2 * j0]        = acc[mt][nt][0] + b0;
            oc1[2 * j0]        = acc[mt][nt][1] + b1;
            oc0[2 * (j0 + 8)]  = acc[mt][nt][2] + b0;
            oc1[2 * (j0 + 8)]  = acc[mt][nt][3] + b1;
        }
    }
}

// =================== launch ===================
extern "C" void kernel_launch(void* const* d_in, const int* in_sizes, int n_in,
                              void* d_out, int out_size) {
    const float* x = (const float*)d_in[0];
    const float* W = (const float*)d_in[1];
    const float* b = (const float*)d_in[2];
    float* out = (float*)d_out;

    const int SMEM_DYN = 65536 + 1024;
    cudaFuncSetAttribute(tconv_gemm, cudaFuncAttributeMaxDynamicSharedMemorySize, SMEM_DYN);

    convert_x_kernel<<<NB * INH, 256>>>(x);          // 2048 blocks
    build_bext_kernel<<<3072, 256>>>(W);             // 786432 threads
    tconv_gemm<<<4096, 256, SMEM_DYN>>>(b, out);     // (n*32+itile)*4 + parity
}

// round 6
// speedup vs baseline: 3.6645x; 1.3852x over previous
#include <cuda_runtime.h>
#include <cuda_fp16.h>
#include <cstdint>

#define NB    32
#define CIN   128
#define COUT  128
#define INH   64
#define INW   64
#define OUTHW 16384   // 128*128

// ---------------- scratch (device globals: allocation-free) ----------------
__device__ __half g_xhi[(size_t)NB * INH * INW * CIN];   // NHWC  fp16(x)
__device__ __half g_xlo[(size_t)NB * INH * INW * CIN];   // NHWC  fp16(x - xh)
__device__ __half g_bext[(size_t)4 * COUT * 512];        // [par][co][k] fp16(W)

// ---------------- helpers ----------------
__device__ __forceinline__ uint32_t smem_u32(const void* p) {
    uint32_t a;
    asm("{ .reg .u64 t; cvta.to.shared.u64 t, %1; cvt.u32.u64 %0, t; }" : "=r"(a) : "l"(p));
    return a;
}
__device__ __forceinline__ void cp_async16(uint32_t dst, const void* src, uint32_t sz) {
    asm volatile("cp.async.cg.shared.global [%0], [%1], 16, %2;"
                 :: "r"(dst), "l"(src), "r"(sz) : "memory");
}
#define CP_COMMIT() asm volatile("cp.async.commit_group;" ::: "memory")
#define CP_WAIT(n)  asm volatile("cp.async.wait_group %0;" :: "n"(n) : "memory")

__device__ __forceinline__ void ldsm_x4(uint32_t* r, uint32_t addr) {
    asm volatile("ldmatrix.sync.aligned.m8n8.x4.shared.b16 {%0,%1,%2,%3}, [%4];"
                 : "=r"(r[0]), "=r"(r[1]), "=r"(r[2]), "=r"(r[3]) : "r"(addr));
}
__device__ __forceinline__ void mma_fp16(float* c, const uint32_t* a, const uint32_t* b) {
    asm volatile(
        "mma.sync.aligned.m16n8k16.row.col.f32.f16.f16.f32 "
        "{%0,%1,%2,%3}, {%4,%5,%6,%7}, {%8,%9}, {%0,%1,%2,%3};"
        : "+f"(c[0]), "+f"(c[1]), "+f"(c[2]), "+f"(c[3])
        : "r"(a[0]), "r"(a[1]), "r"(a[2]), "r"(a[3]), "r"(b[0]), "r"(b[1]));
}

// =================== kernel 1: x fp32 NCHW -> fp16 hi/lo NHWC ===================
__global__ __launch_bounds__(256) void convert_x_kernel(const float* __restrict__ x) {
    __shared__ float tile[128][65];
    const int bid = blockIdx.x;
    const int n = bid >> 6, ihh = bid & 63;
    const int tid = threadIdx.x;

#pragma unroll 4
    for (int e = 0; e < 32; ++e) {
        int flat = e * 256 + tid;
        int ci = flat >> 6, iw = flat & 63;
        tile[ci][iw] = x[(((size_t)n * CIN + ci) * INH + ihh) * INW + iw];
    }
    __syncthreads();
    const size_t ob = (((size_t)n * INH + ihh) * INW) * CIN;
#pragma unroll 4
    for (int e = 0; e < 32; ++e) {
        int flat = e * 256 + tid;
        int iw = flat >> 7, ci = flat & 127;
        float v = tile[ci][iw];
        __half hv = __float2half_rn(v);
        __half lv = __float2half_rn(v - __half2float(hv));
        g_xhi[ob + (size_t)iw * CIN + ci] = hv;
        g_xlo[ob + (size_t)iw * CIN + ci] = lv;
    }
}

// =================== kernel 2: B_ext [par][co][k=512] = fp16(W) ===================
// k = t*128 + ci ; tap t = (dh,dw), kernel coords kh = ph+2dh, kw = pw+2dw.
__global__ __launch_bounds__(256) void build_bext_kernel(const float* __restrict__ W) {
    const int idx = blockIdx.x * 256 + threadIdx.x;   // < 262144
    const int k = idx & 511;
    const int rco = idx >> 9;
    const int co = rco & 127, par = rco >> 7;
    const int t = k >> 7, ci = k & 127;
    const int dh = t >> 1, dw = t & 1, ph = par >> 1, pw = par & 1;
    const int kh = ph + 2 * dh, kw = pw + 2 * dw;
    g_bext[idx] = __float2half_rn(W[(((size_t)(kh * 4 + kw)) * CIN + ci) * COUT + co]);
}

// =================== kernel 3: mma.sync GEMM ===================
// Block = (parity, n, itile). M=128 (2 i-rows x 64 j), N=128 co.
// K' = 1024 (2 fp16-split terms x 512), 16 chunks of 64.
// Chunk c: s=c>>3 selects xh/xl, tap t=(c>>1)&3, ci-half h=c&1; B kb=(c&7)*64.
// 8 warps: warp_m = wid>>2 (2), warp_n = wid&3 (4). Warp tile 64x32 = 4x4 m16n8k16.
__global__ __launch_bounds__(256, 2) void tconv_gemm(const float* __restrict__ bias,
                                                     float* __restrict__ out) {
    extern __shared__ char dynsmem[];
    const uint32_t tiles = (smem_u32(dynsmem) + 1023u) & ~1023u;  // 64KB, 2 stages

    const int tid = threadIdx.x, wid = tid >> 5, lane = tid & 31;
    const int blk = blockIdx.x;
    const int par = blk & 3, rest = blk >> 2;
    const int itile = rest & 31, n = rest >> 5;
    const int ph = par >> 1, pw = par & 1;
    const int warp_m = wid >> 2, warp_n = wid & 3;

    float acc[4][4][4];
#pragma unroll
    for (int mt = 0; mt < 4; ++mt)
#pragma unroll
        for (int nt = 0; nt < 4; ++nt)
#pragma unroll
            for (int q = 0; q < 4; ++q) acc[mt][nt][q] = 0.f;

    // ---- cp.async tile issue for chunk c into stage c&1 ----
    auto issue = [&](int c) {
        const int s = c >> 3, t = (c >> 1) & 3, h = c & 1;
        const int dh = t >> 1, dw = t & 1;
        const uint32_t abase = tiles + (uint32_t)(c & 1) * 32768u;
        const uint32_t bbase = abase + 16384u;
        const __half* xs = s ? g_xlo : g_xhi;
        const int ih_off = itile * 2 + ph - 1 + dh;
        const int iw_off = pw - 1 + dw;
        const int kb = (c & 7) * 64;
#pragma unroll
        for (int e = 0; e < 8; ++e) {
            const int idx = e * 256 + tid;
            const int row = (idx >> 3) & 127, s16 = idx & 7;
            uint32_t so = (uint32_t)(row * 128 + s16 * 16);
            so ^= (so >> 3) & 0x70;                       // SW128 swizzle
            if (idx < 1024) {                             // A: 128 m-rows x 64 k
                const int i_loc = row >> 6, j = row & 63;
                const unsigned ihx = (unsigned)(ih_off + i_loc);
                const unsigned iwx = (unsigned)(iw_off + j);
                const bool ok = (ihx < 64u) & (iwx < 64u);
                const __half* src = ok
                    ? xs + (((size_t)n * INH + ihx) * INW + iwx) * CIN + h * 64 + s16 * 8
                    : xs;                                 // valid dummy, sz=0 zero-fills
                cp_async16(abase + so, src, ok ? 16u : 0u);
            } else {                                      // B: 128 co-rows x 64 k
                const __half* src =
                    g_bext + ((size_t)(par * COUT + row)) * 512 + kb + s16 * 8;
                cp_async16(bbase + so, src, 16u);
            }
        }
        CP_COMMIT();
    };

    // ---- compute chunk c from stage c&1 ----
    auto compute = [&](int c) {
        const uint32_t abase = tiles + (uint32_t)(c & 1) * 32768u;
        const uint32_t bbase = abase + 16384u;
        const int arow = warp_m * 64 + (lane & 15);       // + mt*16
        const int acp0 = lane >> 4;                       // + 2*s
        const int bmtx = lane >> 3, brlo = lane & 7;
        const int brow0 = warp_n * 32 + ((bmtx >> 1) << 3) + brlo;   // + p*16
        const int bcp0 = bmtx & 1;                        // + 2*s
#pragma unroll
        for (int s = 0; s < 4; ++s) {
            uint32_t a[4][4];
#pragma unroll
            for (int mt = 0; mt < 4; ++mt) {
                const int r = arow + mt * 16;
                const uint32_t chunk = (uint32_t)((acp0 + 2 * s) ^ (r & 7));
                ldsm_x4(a[mt], abase + (uint32_t)r * 128u + chunk * 16u);
            }
            uint32_t b[2][4];                             // p -> {b0n0,b1n0,b0n1,b1n1}
#pragma unroll
            for (int p = 0; p < 2; ++p) {
                const int r = brow0 + p * 16;
                const uint32_t chunk = (uint32_t)((bcp0 + 2 * s) ^ (r & 7));
                ldsm_x4(b[p], bbase + (uint32_t)r * 128u + chunk * 16u);
            }
#pragma unroll
            for (int mt = 0; mt < 4; ++mt)
#pragma unroll
                for (int nt = 0; nt < 4; ++nt)
                    mma_fp16(acc[mt][nt], a[mt], &b[nt >> 1][(nt & 1) * 2]);
        }
    };

    issue(0);
    issue(1);
#pragma unroll 1
    for (int c = 0; c < 16; ++c) {
        if (c < 15) { CP_WAIT(1); } else { CP_WAIT(0); }
        __syncthreads();
        compute(c);
        __syncthreads();
        if (c + 2 < 16) issue(c + 2);
    }

    // ---- epilogue: registers -> gmem ----
    // acc reg q: q0:(g, 2t) q1:(g, 2t+1) q2:(g+8, 2t) q3:(g+8, 2t+1)
    const int g = lane >> 2, tg = lane & 3;
    const int oh0 = 2 * (itile * 2 + warp_m) + ph;        // i_loc == warp_m for all rows
    float* const ob = out + (size_t)n * COUT * OUTHW + (size_t)oh0 * 128 + pw;
#pragma unroll
    for (int nt = 0; nt < 4; ++nt) {
        const int co = warp_n * 32 + nt * 8 + 2 * tg;
        const float b0 = __ldg(&bias[co]), b1 = __ldg(&bias[co + 1]);
        float* const oc0 = ob + (size_t)co * OUTHW;
        float* const oc1 = oc0 + OUTHW;
#pragma unroll
        for (int mt = 0; mt < 4; ++mt) {
            const int j0 = mt * 16 + g;                   // j of rows (g) ; j0+8 for g+8
            oc0[2 * j0]        = acc[mt][nt][0] + b0;
            oc1[2 * j0]        = acc[mt][nt][1] + b1;
            oc0[2 * (j0 + 8)]  = acc[mt][nt][2] + b0;
            oc1[2 * (j0 + 8)]  = acc[mt][nt][3] + b1;
        }
    }
}

// =================== launch ===================
extern "C" void kernel_launch(void* const* d_in, const int* in_sizes, int n_in,
                              void* d_out, int out_size) {
    const float* x = (const float*)d_in[0];
    const float* W = (const float*)d_in[1];
    const float* b = (const float*)d_in[2];
    float* out = (float*)d_out;

    const int SMEM_DYN = 65536 + 1024;
    cudaFuncSetAttribute(tconv_gemm, cudaFuncAttributeMaxDynamicSharedMemorySize, SMEM_DYN);

    convert_x_kernel<<<NB * INH, 256>>>(x);          // 2048 blocks
    build_bext_kernel<<<1024, 256>>>(W);             // 262144 threads
    tconv_gemm<<<4096, 256, SMEM_DYN>>>(b, out);     // (n*32+itile)*4 + parity
}

// round 7
// speedup vs baseline: 5.9738x; 1.6302x over previous
#include <cuda_runtime.h>
#include <cuda_fp16.h>
#include <cstdint>

#define NB    32
#define CIN   128
#define COUT  128
#define INH   64
#define INW   64
#define OUTHW 16384   // 128*128

// ---------------- scratch (device globals: allocation-free) ----------------
__device__ __half g_xh[(size_t)NB * INH * INW * CIN];    // NHWC  fp16(x)
__device__ __half g_bext[(size_t)4 * COUT * 512];        // [par][co][k] fp16(W)

// ---------------- helpers ----------------
__device__ __forceinline__ uint32_t smem_u32(const void* p) {
    uint32_t a;
    asm("{ .reg .u64 t; cvta.to.shared.u64 t, %1; cvt.u32.u64 %0, t; }" : "=r"(a) : "l"(p));
    return a;
}
__device__ __forceinline__ void cp_async16(uint32_t dst, const void* src, uint32_t sz) {
    asm volatile("cp.async.cg.shared.global [%0], [%1], 16, %2;"
                 :: "r"(dst), "l"(src), "r"(sz) : "memory");
}
#define CP_COMMIT() asm volatile("cp.async.commit_group;" ::: "memory")
#define CP_WAIT(n)  asm volatile("cp.async.wait_group %0;" :: "n"(n) : "memory")

__device__ __forceinline__ void ldsm_x4(uint32_t* r, uint32_t addr) {
    asm volatile("ldmatrix.sync.aligned.m8n8.x4.shared.b16 {%0,%1,%2,%3}, [%4];"
                 : "=r"(r[0]), "=r"(r[1]), "=r"(r[2]), "=r"(r[3]) : "r"(addr));
}
__device__ __forceinline__ void mma_fp16(float* c, const uint32_t* a, const uint32_t* b) {
    asm volatile(
        "mma.sync.aligned.m16n8k16.row.col.f32.f16.f16.f32 "
        "{%0,%1,%2,%3}, {%4,%5,%6,%7}, {%8,%9}, {%0,%1,%2,%3};"
        : "+f"(c[0]), "+f"(c[1]), "+f"(c[2]), "+f"(c[3])
        : "r"(a[0]), "r"(a[1]), "r"(a[2]), "r"(a[3]), "r"(b[0]), "r"(b[1]));
}

// =================== kernel 1: x fp32 NCHW -> fp16 NHWC ===================
__global__ __launch_bounds__(256) void convert_x_kernel(const float* __restrict__ x) {
    __shared__ float tile[128][65];
    const int bid = blockIdx.x;
    const int n = bid >> 6, ihh = bid & 63;
    const int tid = threadIdx.x;

#pragma unroll 4
    for (int e = 0; e < 32; ++e) {
        int flat = e * 256 + tid;
        int ci = flat >> 6, iw = flat & 63;
        tile[ci][iw] = x[(((size_t)n * CIN + ci) * INH + ihh) * INW + iw];
    }
    __syncthreads();
    const size_t ob = (((size_t)n * INH + ihh) * INW) * CIN;
#pragma unroll 4
    for (int e = 0; e < 16; ++e) {            // 4096 half2 = 16*256
        int flat = e * 256 + tid;
        int iw = flat >> 6, ci2 = flat & 63;  // ci pair
        __half2 h = __floats2half2_rn(tile[2 * ci2][iw], tile[2 * ci2 + 1][iw]);
        *reinterpret_cast<__half2*>(g_xh + ob + (size_t)iw * CIN + 2 * ci2) = h;
    }
}

// =================== kernel 2: B_ext [par][co][k=512] = fp16(W) ===================
// k = t*128 + ci ; tap t = (dh,dw), kernel coords kh = ph+2dh, kw = pw+2dw.
__global__ __launch_bounds__(256) void build_bext_kernel(const float* __restrict__ W) {
    const int idx = blockIdx.x * 256 + threadIdx.x;   // < 262144
    const int k = idx & 511;
    const int rco = idx >> 9;
    const int co = rco & 127, par = rco >> 7;
    const int t = k >> 7, ci = k & 127;
    const int dh = t >> 1, dw = t & 1, ph = par >> 1, pw = par & 1;
    const int kh = ph + 2 * dh, kw = pw + 2 * dw;
    g_bext[idx] = __float2half_rn(W[(((size_t)(kh * 4 + kw)) * CIN + ci) * COUT + co]);
}

// =================== kernel 3: mma.sync GEMM ===================
// Block = (parity, n, itile). M=128 (2 i-rows x 64 j), N=128 co.
// K' = 512 (4 taps x 128 ci), 8 chunks of 64. Chunk c: tap t=c>>1, ci-half h=c&1.
// 8 warps: warp_m = wid>>2 (2), warp_n = wid&3 (4). Warp tile 64x32 = 4x4 m16n8k16.
__global__ __launch_bounds__(256, 2) void tconv_gemm(const float* __restrict__ bias,
                                                     float* __restrict__ out) {
    extern __shared__ char dynsmem[];
    const uint32_t tiles = (smem_u32(dynsmem) + 1023u) & ~1023u;  // 64KB, 2 stages

    const int tid = threadIdx.x, wid = tid >> 5, lane = tid & 31;
    const int blk = blockIdx.x;
    const int par = blk & 3, rest = blk >> 2;
    const int itile = rest & 31, n = rest >> 5;
    const int ph = par >> 1, pw = par & 1;
    const int warp_m = wid >> 2, warp_n = wid & 3;

    float acc[4][4][4];
#pragma unroll
    for (int mt = 0; mt < 4; ++mt)
#pragma unroll
        for (int nt = 0; nt < 4; ++nt)
#pragma unroll
            for (int q = 0; q < 4; ++q) acc[mt][nt][q] = 0.f;

    // ---- cp.async tile issue for chunk c into stage c&1 ----
    auto issue = [&](int c) {
        const int t = c >> 1, h = c & 1;
        const int dh = t >> 1, dw = t & 1;
        const uint32_t abase = tiles + (uint32_t)(c & 1) * 32768u;
        const uint32_t bbase = abase + 16384u;
        const int ih_off = itile * 2 + ph - 1 + dh;
        const int iw_off = pw - 1 + dw;
        const int kb = c * 64;
#pragma unroll
        for (int e = 0; e < 8; ++e) {
            const int idx = e * 256 + tid;
            const int row = (idx >> 3) & 127, s16 = idx & 7;
            uint32_t so = (uint32_t)(row * 128 + s16 * 16);
            so ^= (so >> 3) & 0x70;                       // SW128 swizzle
            if (idx < 1024) {                             // A: 128 m-rows x 64 k
                const int i_loc = row >> 6, j = row & 63;
                const unsigned ihx = (unsigned)(ih_off + i_loc);
                const unsigned iwx = (unsigned)(iw_off + j);
                const bool ok = (ihx < 64u) & (iwx < 64u);
                const __half* src = ok
                    ? g_xh + (((size_t)n * INH + ihx) * INW + iwx) * CIN + h * 64 + s16 * 8
                    : g_xh;                               // valid dummy, sz=0 zero-fills
                cp_async16(abase + so, src, ok ? 16u : 0u);
            } else {                                      // B: 128 co-rows x 64 k
                const __half* src =
                    g_bext + ((size_t)(par * COUT + row)) * 512 + kb + s16 * 8;
                cp_async16(bbase + so, src, 16u);
            }
        }
        CP_COMMIT();
    };

    // ---- compute chunk c from stage c&1 ----
    auto compute = [&](int c) {
        const uint32_t abase = tiles + (uint32_t)(c & 1) * 32768u;
        const uint32_t bbase = abase + 16384u;
        const int arow = warp_m * 64 + (lane & 15);       // + mt*16
        const int acp0 = lane >> 4;                       // + 2*s
        const int bmtx = lane >> 3, brlo = lane & 7;
        const int brow0 = warp_n * 32 + ((bmtx >> 1) << 3) + brlo;   // + p*16
        const int bcp0 = bmtx & 1;                        // + 2*s
#pragma unroll
        for (int s = 0; s < 4; ++s) {
            uint32_t a[4][4];
#pragma unroll
            for (int mt = 0; mt < 4; ++mt) {
                const int r = arow + mt * 16;
                const uint32_t chunk = (uint32_t)((acp0 + 2 * s) ^ (r & 7));
                ldsm_x4(a[mt], abase + (uint32_t)r * 128u + chunk * 16u);
            }
            uint32_t b[2][4];                             // p -> {b0n0,b1n0,b0n1,b1n1}
#pragma unroll
            for (int p = 0; p < 2; ++p) {
                const int r = brow0 + p * 16;
                const uint32_t chunk = (uint32_t)((bcp0 + 2 * s) ^ (r & 7));
                ldsm_x4(b[p], bbase + (uint32_t)r * 128u + chunk * 16u);
            }
#pragma unroll
            for (int mt = 0; mt < 4; ++mt)
#pragma unroll
                for (int nt = 0; nt < 4; ++nt)
                    mma_fp16(acc[mt][nt], a[mt], &b[nt >> 1][(nt & 1) * 2]);
        }
    };

    issue(0);
    issue(1);
#pragma unroll 1
    for (int c = 0; c < 8; ++c) {
        if (c < 7) { CP_WAIT(1); } else { CP_WAIT(0); }
        __syncthreads();
        compute(c);
        __syncthreads();
        if (c + 2 < 8) issue(c + 2);
    }

    // ---- epilogue: registers -> gmem ----
    // acc reg q: q0:(g, 2t) q1:(g, 2t+1) q2:(g+8, 2t) q3:(g+8, 2t+1)
    const int g = lane >> 2, tg = lane & 3;
    const int oh0 = 2 * (itile * 2 + warp_m) + ph;        // i_loc == warp_m for all rows
    float* const ob = out + (size_t)n * COUT * OUTHW + (size_t)oh0 * 128 + pw;
#pragma unroll
    for (int nt = 0; nt < 4; ++nt) {
        const int co = warp_n * 32 + nt * 8 + 2 * tg;
        const float b0 = __ldg(&bias[co]), b1 = __ldg(&bias[co + 1]);
        float* const oc0 = ob + (size_t)co * OUTHW;
        float* const oc1 = oc0 + OUTHW;
#pragma unroll
        for (int mt = 0; mt < 4; ++mt) {
            const int j0 = mt * 16 + g;                   // j of rows (g) ; j0+8 for g+8
            oc0[2 * j0]        = acc[mt][nt][0] + b0;
            oc1[2 * j0]        = acc[mt][nt][1] + b1;
            oc0[2 * (j0 + 8)]  = acc[mt][nt][2] + b0;
            oc1[2 * (j0 + 8)]  = acc[mt][nt][3] + b1;
        }
    }
}

// =================== launch ===================
extern "C" void kernel_launch(void* const* d_in, const int* in_sizes, int n_in,
                              void* d_out, int out_size) {
    const float* x = (const float*)d_in[0];
    const float* W = (const float*)d_in[1];
    const float* b = (const float*)d_in[2];
    float* out = (float*)d_out;

    const int SMEM_DYN = 65536 + 1024;
    cudaFuncSetAttribute(tconv_gemm, cudaFuncAttributeMaxDynamicSharedMemorySize, SMEM_DYN);

    convert_x_kernel<<<NB * INH, 256>>>(x);          // 2048 blocks
    build_bext_kernel<<<1024, 256>>>(W);             // 262144 threads
    tconv_gemm<<<4096, 256, SMEM_DYN>>>(b, out);     // (n*32+itile)*4 + parity
}

// round 8
// speedup vs baseline: 6.2281x; 1.0426x over previous
#include <cuda_runtime.h>
#include <cuda_fp16.h>
#include <cstdint>

#define NB    32
#define CIN   128
#define COUT  128
#define INH   64
#define INW   64
#define OUTHW 16384   // 128*128

// ---------------- scratch (device globals: allocation-free) ----------------
__device__ __half g_xh[(size_t)NB * INH * INW * CIN];    // NHWC  fp16(x)
__device__ __half g_bext[(size_t)4 * COUT * 512];        // [par][co][k] fp16(W)

// ---------------- helpers ----------------
__device__ __forceinline__ uint32_t smem_u32(const void* p) {
    uint32_t a;
    asm("{ .reg .u64 t; cvta.to.shared.u64 t, %1; cvt.u32.u64 %0, t; }" : "=r"(a) : "l"(p));
    return a;
}
__device__ __forceinline__ void cp_async16(uint32_t dst, const void* src, uint32_t sz) {
    asm volatile("cp.async.cg.shared.global [%0], [%1], 16, %2;"
                 :: "r"(dst), "l"(src), "r"(sz) : "memory");
}
#define CP_COMMIT() asm volatile("cp.async.commit_group;" ::: "memory")
#define CP_WAIT(n)  asm volatile("cp.async.wait_group %0;" :: "n"(n) : "memory")

__device__ __forceinline__ void ldsm_x4(uint32_t* r, uint32_t addr) {
    asm volatile("ldmatrix.sync.aligned.m8n8.x4.shared.b16 {%0,%1,%2,%3}, [%4];"
                 : "=r"(r[0]), "=r"(r[1]), "=r"(r[2]), "=r"(r[3]) : "r"(addr));
}
__device__ __forceinline__ void mma_fp16(float* c, const uint32_t* a, const uint32_t* b) {
    asm volatile(
        "mma.sync.aligned.m16n8k16.row.col.f32.f16.f16.f32 "
        "{%0,%1,%2,%3}, {%4,%5,%6,%7}, {%8,%9}, {%0,%1,%2,%3};"
        : "+f"(c[0]), "+f"(c[1]), "+f"(c[2]), "+f"(c[3])
        : "r"(a[0]), "r"(a[1]), "r"(a[2]), "r"(a[3]), "r"(b[0]), "r"(b[1]));
}

// =================== kernel 1: x fp32 NCHW -> fp16 NHWC ===================
__global__ __launch_bounds__(256) void convert_x_kernel(const float* __restrict__ x) {
    __shared__ float tile[128][65];
    const int bid = blockIdx.x;
    const int n = bid >> 6, ihh = bid & 63;
    const int tid = threadIdx.x;

#pragma unroll 4
    for (int e = 0; e < 32; ++e) {
        int flat = e * 256 + tid;
        int ci = flat >> 6, iw = flat & 63;
        tile[ci][iw] = x[(((size_t)n * CIN + ci) * INH + ihh) * INW + iw];
    }
    __syncthreads();
    const size_t ob = (((size_t)n * INH + ihh) * INW) * CIN;
#pragma unroll 4
    for (int e = 0; e < 16; ++e) {            // 4096 half2 = 16*256
        int flat = e * 256 + tid;
        int iw = flat >> 6, ci2 = flat & 63;  // ci pair
        __half2 h = __floats2half2_rn(tile[2 * ci2][iw], tile[2 * ci2 + 1][iw]);
        *reinterpret_cast<__half2*>(g_xh + ob + (size_t)iw * CIN + 2 * ci2) = h;
    }
}

// =================== kernel 2: B_ext [par][co][k=512] = fp16(W) ===================
// k = t*128 + ci ; tap t = (dh,dw), kernel coords kh = ph+2dh, kw = pw+2dw.
__global__ __launch_bounds__(256) void build_bext_kernel(const float* __restrict__ W) {
    const int idx = blockIdx.x * 256 + threadIdx.x;   // < 262144
    const int k = idx & 511;
    const int rco = idx >> 9;
    const int co = rco & 127, par = rco >> 7;
    const int t = k >> 7, ci = k & 127;
    const int dh = t >> 1, dw = t & 1, ph = par >> 1, pw = par & 1;
    const int kh = ph + 2 * dh, kw = pw + 2 * dw;
    g_bext[idx] = __float2half_rn(W[(((size_t)(kh * 4 + kw)) * CIN + ci) * COUT + co]);
}

// =================== kernel 3: mma.sync GEMM ===================
// Block = (parity, n, itile). M=128 (2 i-rows x 64 j), N=128 co.
// K' = 512, 8 chunks of 64 (tap t=c>>1, ci-half h=c&1).
// 4 warps (128 thr), 2x2 grid of 64x64 warp tiles: 4(mt) x 8(nt) m16n8k16 each.
// 3-stage cp.async pipeline, ONE barrier per chunk:
//   [wait(c); sync; compute(c); issue(c+2)] — the sync proves all warps finished
//   compute(c-1), the last reader of stage (c+2)%3, so issue is race-free.
__global__ __launch_bounds__(128, 2) void tconv_gemm(const float* __restrict__ bias,
                                                     float* __restrict__ out) {
    extern __shared__ char dynsmem[];
    const uint32_t tiles = (smem_u32(dynsmem) + 1023u) & ~1023u;  // 3 x 32KB stages

    const int tid = threadIdx.x, wid = tid >> 5, lane = tid & 31;
    const int blk = blockIdx.x;
    const int par = blk & 3, rest = blk >> 2;
    const int itile = rest & 31, n = rest >> 5;
    const int ph = par >> 1, pw = par & 1;
    const int warp_m = wid >> 1, warp_n = wid & 1;    // 2x2, 64x64 per warp

    float acc[4][8][4];
#pragma unroll
    for (int mt = 0; mt < 4; ++mt)
#pragma unroll
        for (int nt = 0; nt < 8; ++nt)
#pragma unroll
            for (int q = 0; q < 4; ++q) acc[mt][nt][q] = 0.f;

    // ---- cp.async tile issue for chunk c into stage c%3 ----
    auto issue = [&](int c) {
        const int t = c >> 1, h = c & 1;
        const int dh = t >> 1, dw = t & 1;
        const uint32_t abase = tiles + (uint32_t)(c % 3) * 32768u;
        const uint32_t bbase = abase + 16384u;
        const int ih_off = itile * 2 + ph - 1 + dh;
        const int iw_off = pw - 1 + dw;
        const int kb = c * 64;
#pragma unroll
        for (int e = 0; e < 16; ++e) {
            const int idx = e * 128 + tid;
            const int row = (idx >> 3) & 127, s16 = idx & 7;
            uint32_t so = (uint32_t)(row * 128 + s16 * 16);
            so ^= (so >> 3) & 0x70;                       // SW128 swizzle
            if (idx < 1024) {                             // A: 128 m-rows x 64 k
                const int i_loc = row >> 6, j = row & 63;
                const unsigned ihx = (unsigned)(ih_off + i_loc);
                const unsigned iwx = (unsigned)(iw_off + j);
                const bool ok = (ihx < 64u) & (iwx < 64u);
                const __half* src = ok
                    ? g_xh + (((size_t)n * INH + ihx) * INW + iwx) * CIN + h * 64 + s16 * 8
                    : g_xh;                               // valid dummy, sz=0 zero-fills
                cp_async16(abase + so, src, ok ? 16u : 0u);
            } else {                                      // B: 128 co-rows x 64 k
                const __half* src =
                    g_bext + ((size_t)(par * COUT + row)) * 512 + kb + s16 * 8;
                cp_async16(bbase + so, src, 16u);
            }
        }
        CP_COMMIT();
    };

    // ---- compute chunk c from stage c%3 ----
    auto compute = [&](int c) {
        const uint32_t abase = tiles + (uint32_t)(c % 3) * 32768u;
        const uint32_t bbase = abase + 16384u;
        const int arow = warp_m * 64 + (lane & 15);       // + mt*16
        const int acp0 = lane >> 4;                       // + 2*s
        const int bmtx = lane >> 3, brlo = lane & 7;
        const int brow0 = warp_n * 64 + ((bmtx >> 1) << 3) + brlo;   // + q*16
        const int bcp0 = bmtx & 1;                        // + 2*s
#pragma unroll
        for (int s = 0; s < 4; ++s) {
            uint32_t a[4][4];
#pragma unroll
            for (int mt = 0; mt < 4; ++mt) {
                const int r = arow + mt * 16;
                const uint32_t chunk = (uint32_t)((acp0 + 2 * s) ^ (r & 7));
                ldsm_x4(a[mt], abase + (uint32_t)r * 128u + chunk * 16u);
            }
            uint32_t b[4][4];                             // q -> {b0n0,b1n0,b0n1,b1n1}
#pragma unroll
            for (int q = 0; q < 4; ++q) {
                const int r = brow0 + q * 16;
                const uint32_t chunk = (uint32_t)((bcp0 + 2 * s) ^ (r & 7));
                ldsm_x4(b[q], bbase + (uint32_t)r * 128u + chunk * 16u);
            }
#pragma unroll
            for (int mt = 0; mt < 4; ++mt)
#pragma unroll
                for (int nt = 0; nt < 8; ++nt)
                    mma_fp16(acc[mt][nt], a[mt], &b[nt >> 1][(nt & 1) * 2]);
        }
    };

    issue(0);
    issue(1);
#pragma unroll 1
    for (int c = 0; c < 8; ++c) {
        if (c < 7) { CP_WAIT(1); } else { CP_WAIT(0); }
        __syncthreads();
        compute(c);
        if (c + 2 < 8) issue(c + 2);
    }

    // ---- epilogue: registers -> gmem ----
    // acc reg q: q0:(g, 2t) q1:(g, 2t+1) q2:(g+8, 2t) q3:(g+8, 2t+1)
    const int g = lane >> 2, tg = lane & 3;
    const int oh0 = 2 * (itile * 2 + warp_m) + ph;        // i_loc == warp_m for all rows
    float* const ob = out + (size_t)n * COUT * OUTHW + (size_t)oh0 * 128 + pw;
#pragma unroll
    for (int nt = 0; nt < 8; ++nt) {
        const int co = warp_n * 64 + nt * 8 + 2 * tg;
        const float b0 = __ldg(&bias[co]), b1 = __ldg(&bias[co + 1]);
        float* const oc0 = ob + (size_t)co * OUTHW;
        float* const oc1 = oc0 + OUTHW;
#pragma unroll
        for (int mt = 0; mt < 4; ++mt) {
            const int j0 = mt * 16 + g;                   // j of rows (g) ; j0+8 for g+8
            oc0[2 * j0]        = acc[mt][nt][0] + b0;
            oc1[2 * j0]        = acc[mt][nt][1] + b1;
            oc0[2 * (j0 + 8)]  = acc[mt][nt][2] + b0;
            oc1[2 * (j0 + 8)]  = acc[mt][nt][3] + b1;
        }
    }
}

// =================== launch ===================
extern "C" void kernel_launch(void* const* d_in, const int* in_sizes, int n_in,
                              void* d_out, int out_size) {
    const float* x = (const float*)d_in[0];
    const float* W = (const float*)d_in[1];
    const float* b = (const float*)d_in[2];
    float* out = (float*)d_out;

    const int SMEM_DYN = 3 * 32768 + 1024;   // 3 stages + align pad
    cudaFuncSetAttribute(tconv_gemm, cudaFuncAttributeMaxDynamicSharedMemorySize, SMEM_DYN);

    convert_x_kernel<<<NB * INH, 256>>>(x);          // 2048 blocks
    build_bext_kernel<<<1024, 256>>>(W);             // 262144 threads
    tconv_gemm<<<4096, 128, SMEM_DYN>>>(b, out);     // (n*32+itile)*4 + parity
}